// round 15
// baseline (speedup 1.0000x reference)
#include <cuda_runtime.h>
#include <cuda_fp16.h>
#include <cstdint>

#define BATCH 8
#define SEQ   4096
#define HDIM  512
#define NROWS (BATCH * SEQ)   // 32768
#define NHEAD 64
#define TLEN  64

#define BM 128
#define BN 128
#define BK 64
#define NCHUNK (HDIM / BK)    // 8
#define NKSTEP (HDIM / 16)    // 32
#define WN (HDIM * HDIM)

// GEMM smem: A only, swizzled 128B rows, 3 stages of 16KB
#define SMP_PRM    0
#define SMP_A      512
#define STG_STRIDE 16384
#define SMEM_REQ   (512 + 3 * 16384)       // 49664

// attn smem: 4 tile slots (64 rows x 272B) + P (64 x 144B) + reductions
#define AT_PITCH  272
#define AT_TILE   (64 * AT_PITCH)          // 17408
#define P_OFF     (4 * AT_TILE)            // 69632
#define P_PITCH   144
#define RED_OFF   (P_OFF + 64 * P_PITCH)   // 78848
#define ATTN_SMEM (RED_OFF + 1024)         // 79872

// conv grid split
#define XN4 ((NROWS * HDIM) / 4)           // 4194304
#define WN4 (WN / 4)                       // 65536
#define XB  (XN4 / 256)                    // 16384
#define WB  (WN4 / 256)                    // 256

// ---------------- scratch (device globals; allocation-free) ----------------
__device__ __half g_QKV[3 * NROWS * HDIM];   // Q, K, V (fp16, permuted order)
__device__ __half g_x16[NROWS * HDIM];       // fp16 activations (x, then attn out)
__device__ __half g_Wh[4 * HDIM * HDIM];     // fp16 weights

// ---------------- helpers ----------------
__device__ __forceinline__ uint32_t smem_to_u32(const void* p) {
    uint32_t a;
    asm("{ .reg .u64 t; cvta.to.shared.u64 t, %1; cvt.u32.u64 %0, t; }"
        : "=r"(a) : "l"(p));
    return a;
}
__device__ __forceinline__ void cp16(uint32_t dst, const void* src) {
    asm volatile("cp.async.cg.shared.global [%0], [%1], 16;"
                 :: "r"(dst), "l"(src) : "memory");
}
__device__ __forceinline__ void cp_commit() {
    asm volatile("cp.async.commit_group;" ::: "memory");
}
__device__ __forceinline__ void cp_wait1() {
    asm volatile("cp.async.wait_group 1;" ::: "memory");
}
__device__ __forceinline__ void cp_wait0() {
    asm volatile("cp.async.wait_group 0;" ::: "memory");
}
__device__ __forceinline__ void ldsm4(uint32_t* r, uint32_t addr) {
    asm volatile("ldmatrix.sync.aligned.m8n8.x4.shared.b16 {%0,%1,%2,%3}, [%4];"
                 : "=r"(r[0]), "=r"(r[1]), "=r"(r[2]), "=r"(r[3]) : "r"(addr));
}
__device__ __forceinline__ void ldsm4t(uint32_t* r, uint32_t addr) {
    asm volatile("ldmatrix.sync.aligned.m8n8.x4.trans.shared.b16 {%0,%1,%2,%3}, [%4];"
                 : "=r"(r[0]), "=r"(r[1]), "=r"(r[2]), "=r"(r[3]) : "r"(addr));
}
__device__ __forceinline__ void mma16816(float* d, const uint32_t* a,
                                         const uint32_t b0, const uint32_t b1) {
    asm volatile(
        "mma.sync.aligned.m16n8k16.row.col.f32.f16.f16.f32 "
        "{%0,%1,%2,%3}, {%4,%5,%6,%7}, {%8,%9}, {%0,%1,%2,%3};"
        : "+f"(d[0]), "+f"(d[1]), "+f"(d[2]), "+f"(d[3])
        : "r"(a[0]), "r"(a[1]), "r"(a[2]), "r"(a[3]), "r"(b0), "r"(b1));
}
__device__ __forceinline__ uint32_t packh2(float a, float b) {
    __half2 h = __floats2half2_rn(a, b);
    return *(uint32_t*)&h;
}

// ---------------------------------------------------------------------------
// fused conversion: x (XB blocks) then Wq,Wk,Wv,Wo (WB blocks each) -> fp16
// ---------------------------------------------------------------------------
__global__ void __launch_bounds__(256) conv_all_kernel(
    const float* __restrict__ x,
    const float* __restrict__ Wq, const float* __restrict__ Wk,
    const float* __restrict__ Wv, const float* __restrict__ Wo,
    __half* __restrict__ x16, __half* __restrict__ Wh)
{
    const int bid = blockIdx.x;
    const float* src;
    __half* dst;
    int i;
    if (bid < XB) {
        src = x; dst = x16; i = bid * 256 + threadIdx.x;
    } else {
        const int w = (bid - XB) / WB;
        const int lb = (bid - XB) - w * WB;
        src = (w == 0) ? Wq : (w == 1) ? Wk : (w == 2) ? Wv : Wo;
        dst = Wh + (size_t)w * WN;
        i = lb * 256 + threadIdx.x;
    }
    float4 v = ((const float4*)src)[i];
    uint2 o;
    o.x = packh2(v.x, v.y);
    o.y = packh2(v.z, v.w);
    ((uint2*)dst)[i] = o;
}

// ---------------------------------------------------------------------------
// single-product fp16 GEMM: A via 3-stage cp.async smem pipeline (BK=64,
// swizzled), B fragments loaded DIRECTLY from global (LDG.32, W row-major
// gives exact m16n8k16 col-major fragment halves), prefetched 1 k-step ahead.
// out[m,n] = sum_k A[rowmap(m),k]*W[n,k] + bias[n]; blockIdx.z selects slice.
// ---------------------------------------------------------------------------
__global__ void __launch_bounds__(256, 2) mma_gemm_kernel(
    const __half* __restrict__ A16, const __half* __restrict__ Wbase,
    const float* __restrict__ b0p, const float* __restrict__ b1p,
    const float* __restrict__ b2p, float* __restrict__ outf,
    __half* __restrict__ outhBase, const int* __restrict__ perm, int use_perm)
{
    extern __shared__ char smem[];
    const uint32_t sb = smem_to_u32(smem);
    int* prm = (int*)(smem + SMP_PRM);

    const int z = blockIdx.z;
    const __half* Bh = Wbase + (size_t)z * WN;
    const float* bias = (z == 0) ? b0p : (z == 1) ? b1p : b2p;

    const int tid = threadIdx.x;
    const int lid = tid & 31;
    const int wid = tid >> 5;
    const int wm  = wid & 1;
    const int wn  = wid >> 1;

    const int n0 = blockIdx.x * BN;
    const int m0 = blockIdx.y * BM;
    const int b  = m0 / SEQ;
    const int i0 = m0 % SEQ;

    if (tid < BM)
        prm[tid] = b * SEQ + (use_perm ? perm[i0 + tid] : (i0 + tid));
    __syncthreads();

    // ---- A staging: rows r0+32i (i=0..3), 16B chunk c of the 128B row ----
    const int r0 = tid >> 3;          // 0..31
    const int c  = tid & 7;           // 0..7
    const __half* aSrc[4];
    #pragma unroll
    for (int i = 0; i < 4; i++)
        aSrc[i] = A16 + (size_t)prm[r0 + 32 * i] * HDIM + c * 8;
    const uint32_t dsw = (uint32_t)r0 * 128 + (uint32_t)((c ^ (r0 & 7)) << 4);

    // ---- A ldsm lane addressing (swizzled) ----
    const uint32_t lr  = (lid & 15);
    const uint32_t hib = (lid >> 4) & 1;
    const uint32_t xr  = lr & 7;
    const uint32_t aRow = (wm * 64 + lr) * 128;

    // ---- B global fragment base: n = n0 + wn*32 + idx*8 + lid>>2,
    //      k halves at (lid&3)*2 (+8 for hi half), advancing 16 per k-step ----
    const __half* bPtr = Bh + (size_t)(n0 + wn * 32 + (lid >> 2)) * HDIM
                            + (lid & 3) * 2;

    float acc[4][4][4];
    #pragma unroll
    for (int i = 0; i < 4; i++)
        #pragma unroll
        for (int j = 0; j < 4; j++)
            #pragma unroll
            for (int q = 0; q < 4; q++) acc[i][j][q] = 0.f;

    #define GSTAGE(sidx, ko) do { \
        const uint32_t aB_ = sb + SMP_A + (sidx) * STG_STRIDE; \
        _Pragma("unroll") \
        for (int i_ = 0; i_ < 4; i_++) \
            cp16(aB_ + dsw + i_ * 4096, aSrc[i_] + (ko)); \
    } while (0)

    #define LOADB(buf, kk) do { \
        const __half* bk_ = bPtr + (kk) * 16; \
        _Pragma("unroll") \
        for (int i_ = 0; i_ < 4; i_++) { \
            bfrag[buf][i_ * 2 + 0] = *(const uint32_t*)(bk_ + (size_t)(i_ * 8) * HDIM); \
            bfrag[buf][i_ * 2 + 1] = *(const uint32_t*)(bk_ + (size_t)(i_ * 8) * HDIM + 8); \
        } } while (0)

    // prologue: stage A chunks 0,1; load B fragments for k-step 0
    GSTAGE(0, 0);           cp_commit();
    GSTAGE(1, (size_t)BK);  cp_commit();

    uint32_t bfrag[2][8];
    LOADB(0, 0);

    int rd = 0, wr = 2;
    for (int ch = 0; ch < NCHUNK; ch++) {
        cp_wait1();          // A chunk ch resident
        __syncthreads();     // buffer wr free

        if (ch + 2 < NCHUNK)
            GSTAGE(wr, (size_t)(ch + 2) * BK);
        cp_commit();         // unconditional: exact group accounting

        const uint32_t aB = sb + SMP_A + rd * STG_STRIDE;

        #pragma unroll
        for (int ks = 0; ks < 4; ks++) {
            const int kk = ch * 4 + ks;
            const int cur = kk & 1;
            if (kk + 1 < NKSTEP)
                LOADB(cur ^ 1, kk + 1);   // prefetch next k-step's B
            const uint32_t sw = (((ks * 2 + hib) ^ xr) << 4);
            uint32_t ah[4][4];
            #pragma unroll
            for (int mf = 0; mf < 4; mf++)
                ldsm4(ah[mf], aB + aRow + mf * (16 * 128) + sw);
            #pragma unroll
            for (int idx = 0; idx < 4; idx++) {
                const uint32_t bb0 = bfrag[cur][idx * 2];
                const uint32_t bb1 = bfrag[cur][idx * 2 + 1];
                #pragma unroll
                for (int mf = 0; mf < 4; mf++)
                    mma16816(acc[mf][idx], ah[mf], bb0, bb1);
            }
        }
        rd = (rd + 1) % 3;
        wr = (wr + 1) % 3;
    }
    #undef GSTAGE
    #undef LOADB

    // ---- epilogue ----
    __half* outh = outhBase ? (outhBase + (size_t)z * NROWS * HDIM) : nullptr;
    #pragma unroll
    for (int mf = 0; mf < 4; mf++) {
        const int row = m0 + wm * 64 + mf * 16 + (lid >> 2);
        #pragma unroll
        for (int nf = 0; nf < 4; nf++) {
            const int col = n0 + wn * 32 + nf * 8 + (lid & 3) * 2;
            const float2 bb = *(const float2*)(bias + col);
            float v00 = acc[mf][nf][0] + bb.x, v01 = acc[mf][nf][1] + bb.y;
            float v10 = acc[mf][nf][2] + bb.x, v11 = acc[mf][nf][3] + bb.y;
            if (outf) {
                *(float2*)(outf + (size_t)row * HDIM + col) = make_float2(v00, v01);
                *(float2*)(outf + (size_t)(row + 8) * HDIM + col) = make_float2(v10, v11);
            } else {
                *(uint32_t*)(outh + (size_t)row * HDIM + col)       = packh2(v00, v01);
                *(uint32_t*)(outh + (size_t)(row + 8) * HDIM + col) = packh2(v10, v11);
            }
        }
    }
}

// ---------------------------------------------------------------------------
// Tensorized block attention: 256 threads / 8 warps (unchanged from R13).
// ---------------------------------------------------------------------------
__global__ void __launch_bounds__(256) attn_kernel(const int* __restrict__ perm)
{
    extern __shared__ char smem[];
    const uint32_t sb = smem_to_u32(smem);
    float* red = (float*)(smem + RED_OFF);
    float* pmax = red;
    float* psum = red + 128;

    const int head = blockIdx.x;
    const int b    = blockIdx.y;
    const int tid  = threadIdx.x;
    const int lid  = tid & 31;
    const int wid  = tid >> 5;
    const int wm   = wid & 3;
    const int wn2  = wid >> 2;

    const size_t tokbase = ((size_t)b * SEQ + head * TLEN) * HDIM;
    const __half* Qg = g_QKV + 0 * (size_t)NROWS * HDIM + tokbase;
    const __half* Kg = g_QKV + 1 * (size_t)NROWS * HDIM + tokbase;
    const __half* Vg = g_QKV + 2 * (size_t)NROWS * HDIM + tokbase;

    const uint32_t lr = lid & 15;
    const uint32_t lkb = ((lid >> 4) & 1) * 16;

    #define STAGE1(dst, src, hc) do { \
        _Pragma("unroll") \
        for (int i_ = 0; i_ < 4; i_++) { \
            int idx_ = tid + i_ * 256; \
            int r_ = idx_ >> 4, cg_ = idx_ & 15; \
            cp16((dst) + r_ * AT_PITCH + cg_ * 16, (src) + (size_t)r_ * HDIM + (hc) + cg_ * 8); \
        } } while (0)

    float sc[4][4];
    #pragma unroll
    for (int i = 0; i < 4; i++)
        #pragma unroll
        for (int q = 0; q < 4; q++) sc[i][q] = 0.f;

    STAGE1(sb + 0 * AT_TILE, Qg, 0);
    STAGE1(sb + 1 * AT_TILE, Kg, 0);
    cp_commit();

    for (int hcb = 0; hcb < 4; hcb++) {
        if (hcb < 3) {
            const uint32_t s = ((hcb + 1) & 1) * 2;
            STAGE1(sb + s * AT_TILE, Qg, (hcb + 1) * 128);
            STAGE1(sb + (s + 1) * AT_TILE, Kg, (hcb + 1) * 128);
            cp_commit();
            cp_wait1();
        } else {
            STAGE1(sb + 0 * AT_TILE, Vg, 0);
            cp_commit();
            cp_wait1();
        }
        __syncthreads();

        const uint32_t qb = sb + ((hcb & 1) * 2) * AT_TILE;
        const uint32_t kb = qb + AT_TILE;
        #pragma unroll
        for (int ks = 0; ks < 8; ks++) {
            uint32_t qh[4];
            ldsm4(qh, qb + (wm * 16 + lr) * AT_PITCH + ks * 32 + lkb);
            #pragma unroll
            for (int p = 0; p < 2; p++) {
                uint32_t kh[4];
                ldsm4(kh, kb + (wn2 * 32 + p * 16 + lr) * AT_PITCH + ks * 32 + lkb);
                mma16816(sc[2 * p],     qh, kh[0], kh[2]);
                mma16816(sc[2 * p + 1], qh, kh[1], kh[3]);
            }
        }
        __syncthreads();
    }

    const int R0 = wm * 16 + (lid >> 2);
    const int R1 = R0 + 8;
    const float scale = 0.04419417382415922f;
    float mx0 = -1e30f, mx1 = -1e30f;
    #pragma unroll
    for (int nf = 0; nf < 4; nf++) {
        #pragma unroll
        for (int q = 0; q < 4; q++) sc[nf][q] *= scale;
        mx0 = fmaxf(mx0, fmaxf(sc[nf][0], sc[nf][1]));
        mx1 = fmaxf(mx1, fmaxf(sc[nf][2], sc[nf][3]));
    }
    mx0 = fmaxf(mx0, __shfl_xor_sync(0xffffffffu, mx0, 1));
    mx0 = fmaxf(mx0, __shfl_xor_sync(0xffffffffu, mx0, 2));
    mx1 = fmaxf(mx1, __shfl_xor_sync(0xffffffffu, mx1, 1));
    mx1 = fmaxf(mx1, __shfl_xor_sync(0xffffffffu, mx1, 2));
    if ((lid & 3) == 0) {
        pmax[R0 * 2 + wn2] = mx0;
        pmax[R1 * 2 + wn2] = mx1;
    }
    __syncthreads();
    const float gm0 = fmaxf(pmax[R0 * 2], pmax[R0 * 2 + 1]);
    const float gm1 = fmaxf(pmax[R1 * 2], pmax[R1 * 2 + 1]);

    float s0 = 0.f, s1 = 0.f;
    #pragma unroll
    for (int nf = 0; nf < 4; nf++) {
        sc[nf][0] = __expf(sc[nf][0] - gm0); s0 += sc[nf][0];
        sc[nf][1] = __expf(sc[nf][1] - gm0); s0 += sc[nf][1];
        sc[nf][2] = __expf(sc[nf][2] - gm1); s1 += sc[nf][2];
        sc[nf][3] = __expf(sc[nf][3] - gm1); s1 += sc[nf][3];
    }
    s0 += __shfl_xor_sync(0xffffffffu, s0, 1);
    s0 += __shfl_xor_sync(0xffffffffu, s0, 2);
    s1 += __shfl_xor_sync(0xffffffffu, s1, 1);
    s1 += __shfl_xor_sync(0xffffffffu, s1, 2);
    if ((lid & 3) == 0) {
        psum[R0 * 2 + wn2] = s0;
        psum[R1 * 2 + wn2] = s1;
    }
    __syncthreads();
    const float inv0 = 1.f / (psum[R0 * 2] + psum[R0 * 2 + 1]);
    const float inv1 = 1.f / (psum[R1 * 2] + psum[R1 * 2 + 1]);

    {
        char* Pp = smem + P_OFF;
        #pragma unroll
        for (int nf = 0; nf < 4; nf++) {
            const int col = wn2 * 32 + nf * 8 + (lid & 3) * 2;
            *(uint32_t*)(Pp + R0 * P_PITCH + col * 2) = packh2(sc[nf][0] * inv0, sc[nf][1] * inv0);
            *(uint32_t*)(Pp + R1 * P_PITCH + col * 2) = packh2(sc[nf][2] * inv1, sc[nf][3] * inv1);
        }
    }
    __syncthreads();

    uint32_t pa[4][4];
    #pragma unroll
    for (int j = 0; j < 4; j++)
        ldsm4(pa[j], sb + P_OFF + (wm * 16 + lr) * P_PITCH + j * 32 + lkb);

    const int prow0 = perm[head * TLEN + R0];
    const int prow8 = perm[head * TLEN + R1];
    const size_t obase0 = ((size_t)b * SEQ + prow0) * HDIM;
    const size_t obase8 = ((size_t)b * SEQ + prow8) * HDIM;

    for (int hcb = 0; hcb < 4; hcb++) {
        if (hcb < 3) {
            STAGE1(sb + ((hcb + 1) & 1) * AT_TILE, Vg, (hcb + 1) * 128);
            cp_commit();
            cp_wait1();
        } else {
            cp_wait0();
        }
        __syncthreads();

        const uint32_t vb = sb + (hcb & 1) * AT_TILE;
        float o[8][4];
        #pragma unroll
        for (int i = 0; i < 8; i++)
            #pragma unroll
            for (int q = 0; q < 4; q++) o[i][q] = 0.f;

        #pragma unroll
        for (int j = 0; j < 4; j++) {
            #pragma unroll
            for (int nf2 = 0; nf2 < 4; nf2++) {
                const uint32_t coff = (wn2 * 64 + nf2 * 16 + ((lid >> 4) & 1) * 8) * 2;
                uint32_t vh[4];
                ldsm4t(vh, vb + (j * 16 + lr) * AT_PITCH + coff);
                mma16816(o[2 * nf2],     pa[j], vh[0], vh[1]);
                mma16816(o[2 * nf2 + 1], pa[j], vh[2], vh[3]);
            }
        }

        const int hc = hcb * 128;
        #pragma unroll
        for (int nf = 0; nf < 8; nf++) {
            const int col = hc + wn2 * 64 + nf * 8 + (lid & 3) * 2;
            *(uint32_t*)(g_x16 + obase0 + col) = packh2(o[nf][0], o[nf][1]);
            *(uint32_t*)(g_x16 + obase8 + col) = packh2(o[nf][2], o[nf][3]);
        }
        __syncthreads();
    }
    #undef STAGE1
}

// ---------------------------------------------------------------------------
extern "C" void kernel_launch(void* const* d_in, const int* in_sizes, int n_in,
                              void* d_out, int out_size)
{
    const float* x  = (const float*)d_in[0];
    const float* Wq = (const float*)d_in[1];
    const float* bq = (const float*)d_in[2];
    const float* Wk = (const float*)d_in[3];
    const float* bk = (const float*)d_in[4];
    const float* Wv = (const float*)d_in[5];
    const float* bv = (const float*)d_in[6];
    const float* Wo = (const float*)d_in[7];
    const float* bo = (const float*)d_in[8];
    const int* perm = (const int*)d_in[9];
    float* out = (float*)d_out;

    __half *x16, *Wh, *qkv;
    cudaGetSymbolAddress((void**)&x16, g_x16);
    cudaGetSymbolAddress((void**)&Wh,  g_Wh);
    cudaGetSymbolAddress((void**)&qkv, g_QKV);

    cudaFuncSetAttribute(mma_gemm_kernel,
                         cudaFuncAttributeMaxDynamicSharedMemorySize, SMEM_REQ);
    cudaFuncSetAttribute(attn_kernel,
                         cudaFuncAttributeMaxDynamicSharedMemorySize, ATTN_SMEM);

    // all conversions in one launch
    conv_all_kernel<<<XB + 4 * WB, 256>>>(x, Wq, Wk, Wv, Wo, x16, Wh);

    // fused QKV projections (grid.z = 0..2) -> g_QKV fp16 (permuted rows)
    mma_gemm_kernel<<<dim3(HDIM / BN, NROWS / BM, 3), 256, SMEM_REQ>>>(
        x16, Wh, bq, bk, bv, nullptr, qkv, perm, 1);

    // tensorized attention -> g_x16 (fp16, un-permuted)
    attn_kernel<<<dim3(NHEAD, BATCH), 256, ATTN_SMEM>>>(perm);

    // output projection -> fp32 out
    mma_gemm_kernel<<<dim3(HDIM / BN, NROWS / BM, 1), 256, SMEM_REQ>>>(
        x16, Wh + 3 * (size_t)WN, bo, bo, bo, out, nullptr, perm, 0);
}

// round 16
// speedup vs baseline: 1.5258x; 1.5258x over previous
#include <cuda_runtime.h>
#include <cuda_fp16.h>
#include <cstdint>

#define BATCH 8
#define SEQ   4096
#define HDIM  512
#define NROWS (BATCH * SEQ)   // 32768
#define NHEAD 64
#define TLEN  64

#define BM 128
#define BN 128
#define BK 64
#define NCHUNK (HDIM / BK)    // 8
#define WN (HDIM * HDIM)

// GEMM smem: swizzled 128B rows, 3 stages of (A 16KB + B 16KB)
#define SMP_PRM    0
#define SMP_A      512
#define SMP_B      (512 + 3 * 16384)
#define STG_STRIDE 16384
#define SMEM_REQ   (512 + 6 * 16384)       // 98816

// attn smem: 4 tile slots (64 rows x 272B) + P (64 x 144B) + reductions
#define AT_PITCH  272
#define AT_TILE   (64 * AT_PITCH)          // 17408
#define P_OFF     (4 * AT_TILE)            // 69632
#define P_PITCH   144
#define RED_OFF   (P_OFF + 64 * P_PITCH)   // 78848
#define ATTN_SMEM (RED_OFF + 1024)         // 79872

// conv grid split: each block converts 1024 float4s (4 per thread, MLP=4)
#define XN4 ((NROWS * HDIM) / 4)           // 4194304
#define WN4 (WN / 4)                       // 65536
#define XB4 (XN4 / 1024)                   // 4096
#define WB4 (WN4 / 1024)                   // 64

// ---------------- scratch (device globals; allocation-free) ----------------
__device__ __half g_QKV[3 * NROWS * HDIM];   // Q, K, V (fp16, permuted order)
__device__ __half g_x16[NROWS * HDIM];       // fp16 activations (x, then attn out)
__device__ __half g_Wh[4 * HDIM * HDIM];     // fp16 weights

// ---------------- helpers ----------------
__device__ __forceinline__ uint32_t smem_to_u32(const void* p) {
    uint32_t a;
    asm("{ .reg .u64 t; cvta.to.shared.u64 t, %1; cvt.u32.u64 %0, t; }"
        : "=r"(a) : "l"(p));
    return a;
}
__device__ __forceinline__ void cp16(uint32_t dst, const void* src) {
    asm volatile("cp.async.cg.shared.global [%0], [%1], 16;"
                 :: "r"(dst), "l"(src) : "memory");
}
__device__ __forceinline__ void cp_commit() {
    asm volatile("cp.async.commit_group;" ::: "memory");
}
__device__ __forceinline__ void cp_wait1() {
    asm volatile("cp.async.wait_group 1;" ::: "memory");
}
__device__ __forceinline__ void cp_wait0() {
    asm volatile("cp.async.wait_group 0;" ::: "memory");
}
__device__ __forceinline__ void ldsm4(uint32_t* r, uint32_t addr) {
    asm volatile("ldmatrix.sync.aligned.m8n8.x4.shared.b16 {%0,%1,%2,%3}, [%4];"
                 : "=r"(r[0]), "=r"(r[1]), "=r"(r[2]), "=r"(r[3]) : "r"(addr));
}
__device__ __forceinline__ void ldsm4t(uint32_t* r, uint32_t addr) {
    asm volatile("ldmatrix.sync.aligned.m8n8.x4.trans.shared.b16 {%0,%1,%2,%3}, [%4];"
                 : "=r"(r[0]), "=r"(r[1]), "=r"(r[2]), "=r"(r[3]) : "r"(addr));
}
__device__ __forceinline__ void mma16816(float* d, const uint32_t* a,
                                         const uint32_t b0, const uint32_t b1) {
    asm volatile(
        "mma.sync.aligned.m16n8k16.row.col.f32.f16.f16.f32 "
        "{%0,%1,%2,%3}, {%4,%5,%6,%7}, {%8,%9}, {%0,%1,%2,%3};"
        : "+f"(d[0]), "+f"(d[1]), "+f"(d[2]), "+f"(d[3])
        : "r"(a[0]), "r"(a[1]), "r"(a[2]), "r"(a[3]), "r"(b0), "r"(b1));
}
__device__ __forceinline__ uint32_t packh2(float a, float b) {
    __half2 h = __floats2half2_rn(a, b);
    return *(uint32_t*)&h;
}

// ---------------------------------------------------------------------------
// fused conversion with MLP=4: x (XB4 blocks) then Wq,Wk,Wv,Wo (WB4 each)
// ---------------------------------------------------------------------------
__global__ void __launch_bounds__(256) conv_all_kernel(
    const float* __restrict__ x,
    const float* __restrict__ Wq, const float* __restrict__ Wk,
    const float* __restrict__ Wv, const float* __restrict__ Wo,
    __half* __restrict__ x16, __half* __restrict__ Wh)
{
    const int bid = blockIdx.x;
    const float* src;
    __half* dst;
    int base;
    if (bid < XB4) {
        src = x; dst = x16; base = bid * 1024;
    } else {
        const int w = (bid - XB4) / WB4;
        const int lb = (bid - XB4) - w * WB4;
        src = (w == 0) ? Wq : (w == 1) ? Wk : (w == 2) ? Wv : Wo;
        dst = Wh + (size_t)w * WN;
        base = lb * 1024;
    }
    // 4 independent float4 loads per thread (MLP=4 overlaps DRAM latency)
    float4 v[4];
    #pragma unroll
    for (int j = 0; j < 4; j++)
        v[j] = ((const float4*)src)[base + threadIdx.x + j * 256];
    #pragma unroll
    for (int j = 0; j < 4; j++) {
        uint2 o;
        o.x = packh2(v[j].x, v[j].y);
        o.y = packh2(v[j].z, v[j].w);
        ((uint2*)dst)[base + threadIdx.x + j * 256] = o;
    }
}

// ---------------------------------------------------------------------------
// single-product fp16 GEMM, BK=64, swizzled smem, 3-stage cp.async pipeline,
// ONE __syncthreads per chunk (R13-proven optimum shape).
// out[m,n] = sum_k A[rowmap(m),k]*W[n,k] + bias[n]; blockIdx.z selects slice.
// ---------------------------------------------------------------------------
__global__ void __launch_bounds__(256, 2) mma_gemm_kernel(
    const __half* __restrict__ A16, const __half* __restrict__ Wbase,
    const float* __restrict__ b0p, const float* __restrict__ b1p,
    const float* __restrict__ b2p, float* __restrict__ outf,
    __half* __restrict__ outhBase, const int* __restrict__ perm, int use_perm)
{
    extern __shared__ char smem[];
    const uint32_t sb = smem_to_u32(smem);
    int* prm = (int*)(smem + SMP_PRM);

    const int z = blockIdx.z;
    const __half* Bh = Wbase + (size_t)z * WN;
    const float* bias = (z == 0) ? b0p : (z == 1) ? b1p : b2p;

    const int tid = threadIdx.x;
    const int lid = tid & 31;
    const int wid = tid >> 5;
    const int wm  = wid & 1;
    const int wn  = wid >> 1;

    const int n0 = blockIdx.x * BN;
    const int m0 = blockIdx.y * BM;
    const int b  = m0 / SEQ;
    const int i0 = m0 % SEQ;

    if (tid < BM)
        prm[tid] = b * SEQ + (use_perm ? perm[i0 + tid] : (i0 + tid));
    __syncthreads();

    // ---- staging setup: rows r0+32i (i=0..3), 16B chunk c of the 128B row ----
    const int r0 = tid >> 3;          // 0..31
    const int c  = tid & 7;           // 0..7
    const __half* aSrc[4];
    const __half* bSrc[4];
    #pragma unroll
    for (int i = 0; i < 4; i++) {
        aSrc[i] = A16 + (size_t)prm[r0 + 32 * i] * HDIM + c * 8;
        bSrc[i] = Bh + (size_t)(n0 + r0 + 32 * i) * HDIM + c * 8;
    }
    const uint32_t dsw = (uint32_t)r0 * 128 + (uint32_t)((c ^ (r0 & 7)) << 4);

    // ---- ldsm lane addressing (swizzled) ----
    const uint32_t lr  = (lid & 15);
    const uint32_t hib = (lid >> 4) & 1;
    const uint32_t xr  = lr & 7;
    const uint32_t aRow = (wm * 64 + lr) * 128;
    const uint32_t bRow = (wn * 32 + lr) * 128;

    float acc[4][4][4];
    #pragma unroll
    for (int i = 0; i < 4; i++)
        #pragma unroll
        for (int j = 0; j < 4; j++)
            #pragma unroll
            for (int q = 0; q < 4; q++) acc[i][j][q] = 0.f;

    #define GSTAGE(sidx, ko) do { \
        const uint32_t aB_ = sb + SMP_A + (sidx) * STG_STRIDE; \
        const uint32_t bB_ = sb + SMP_B + (sidx) * STG_STRIDE; \
        _Pragma("unroll") \
        for (int i_ = 0; i_ < 4; i_++) { \
            cp16(aB_ + dsw + i_ * 4096, aSrc[i_] + (ko)); \
            cp16(bB_ + dsw + i_ * 4096, bSrc[i_] + (ko)); \
        } \
    } while (0)

    // prologue: stage chunks 0 and 1
    GSTAGE(0, 0);           cp_commit();
    GSTAGE(1, (size_t)BK);  cp_commit();

    int rd = 0, wr = 2;
    for (int ch = 0; ch < NCHUNK; ch++) {
        cp_wait1();          // chunk ch resident
        __syncthreads();     // buffer wr free

        if (ch + 2 < NCHUNK)
            GSTAGE(wr, (size_t)(ch + 2) * BK);
        cp_commit();         // unconditional: exact group accounting

        const uint32_t aB = sb + SMP_A + rd * STG_STRIDE;
        const uint32_t bB = sb + SMP_B + rd * STG_STRIDE;

        #pragma unroll
        for (int ks = 0; ks < 4; ks++) {
            const uint32_t sw = (((ks * 2 + hib) ^ xr) << 4);
            uint32_t ah[4][4];
            #pragma unroll
            for (int mf = 0; mf < 4; mf++)
                ldsm4(ah[mf], aB + aRow + mf * (16 * 128) + sw);
            #pragma unroll
            for (int p = 0; p < 2; p++) {
                uint32_t tb[4];
                ldsm4(tb, bB + bRow + p * (16 * 128) + sw);
                #pragma unroll
                for (int mf = 0; mf < 4; mf++) {
                    mma16816(acc[mf][2 * p],     ah[mf], tb[0], tb[2]);
                    mma16816(acc[mf][2 * p + 1], ah[mf], tb[1], tb[3]);
                }
            }
        }
        rd = (rd + 1) % 3;
        wr = (wr + 1) % 3;
    }
    #undef GSTAGE

    // ---- epilogue ----
    __half* outh = outhBase ? (outhBase + (size_t)z * NROWS * HDIM) : nullptr;
    #pragma unroll
    for (int mf = 0; mf < 4; mf++) {
        const int row = m0 + wm * 64 + mf * 16 + (lid >> 2);
        #pragma unroll
        for (int nf = 0; nf < 4; nf++) {
            const int col = n0 + wn * 32 + nf * 8 + (lid & 3) * 2;
            const float2 bb = *(const float2*)(bias + col);
            float v00 = acc[mf][nf][0] + bb.x, v01 = acc[mf][nf][1] + bb.y;
            float v10 = acc[mf][nf][2] + bb.x, v11 = acc[mf][nf][3] + bb.y;
            if (outf) {
                *(float2*)(outf + (size_t)row * HDIM + col) = make_float2(v00, v01);
                *(float2*)(outf + (size_t)(row + 8) * HDIM + col) = make_float2(v10, v11);
            } else {
                *(uint32_t*)(outh + (size_t)row * HDIM + col)       = packh2(v00, v01);
                *(uint32_t*)(outh + (size_t)(row + 8) * HDIM + col) = packh2(v10, v11);
            }
        }
    }
}

// ---------------------------------------------------------------------------
// Tensorized block attention: 256 threads / 8 warps (unchanged from R13).
// ---------------------------------------------------------------------------
__global__ void __launch_bounds__(256) attn_kernel(const int* __restrict__ perm)
{
    extern __shared__ char smem[];
    const uint32_t sb = smem_to_u32(smem);
    float* red = (float*)(smem + RED_OFF);
    float* pmax = red;
    float* psum = red + 128;

    const int head = blockIdx.x;
    const int b    = blockIdx.y;
    const int tid  = threadIdx.x;
    const int lid  = tid & 31;
    const int wid  = tid >> 5;
    const int wm   = wid & 3;
    const int wn2  = wid >> 2;

    const size_t tokbase = ((size_t)b * SEQ + head * TLEN) * HDIM;
    const __half* Qg = g_QKV + 0 * (size_t)NROWS * HDIM + tokbase;
    const __half* Kg = g_QKV + 1 * (size_t)NROWS * HDIM + tokbase;
    const __half* Vg = g_QKV + 2 * (size_t)NROWS * HDIM + tokbase;

    const uint32_t lr = lid & 15;
    const uint32_t lkb = ((lid >> 4) & 1) * 16;

    #define STAGE1(dst, src, hc) do { \
        _Pragma("unroll") \
        for (int i_ = 0; i_ < 4; i_++) { \
            int idx_ = tid + i_ * 256; \
            int r_ = idx_ >> 4, cg_ = idx_ & 15; \
            cp16((dst) + r_ * AT_PITCH + cg_ * 16, (src) + (size_t)r_ * HDIM + (hc) + cg_ * 8); \
        } } while (0)

    float sc[4][4];
    #pragma unroll
    for (int i = 0; i < 4; i++)
        #pragma unroll
        for (int q = 0; q < 4; q++) sc[i][q] = 0.f;

    STAGE1(sb + 0 * AT_TILE, Qg, 0);
    STAGE1(sb + 1 * AT_TILE, Kg, 0);
    cp_commit();

    for (int hcb = 0; hcb < 4; hcb++) {
        if (hcb < 3) {
            const uint32_t s = ((hcb + 1) & 1) * 2;
            STAGE1(sb + s * AT_TILE, Qg, (hcb + 1) * 128);
            STAGE1(sb + (s + 1) * AT_TILE, Kg, (hcb + 1) * 128);
            cp_commit();
            cp_wait1();
        } else {
            STAGE1(sb + 0 * AT_TILE, Vg, 0);
            cp_commit();
            cp_wait1();
        }
        __syncthreads();

        const uint32_t qb = sb + ((hcb & 1) * 2) * AT_TILE;
        const uint32_t kb = qb + AT_TILE;
        #pragma unroll
        for (int ks = 0; ks < 8; ks++) {
            uint32_t qh[4];
            ldsm4(qh, qb + (wm * 16 + lr) * AT_PITCH + ks * 32 + lkb);
            #pragma unroll
            for (int p = 0; p < 2; p++) {
                uint32_t kh[4];
                ldsm4(kh, kb + (wn2 * 32 + p * 16 + lr) * AT_PITCH + ks * 32 + lkb);
                mma16816(sc[2 * p],     qh, kh[0], kh[2]);
                mma16816(sc[2 * p + 1], qh, kh[1], kh[3]);
            }
        }
        __syncthreads();
    }

    const int R0 = wm * 16 + (lid >> 2);
    const int R1 = R0 + 8;
    const float scale = 0.04419417382415922f;
    float mx0 = -1e30f, mx1 = -1e30f;
    #pragma unroll
    for (int nf = 0; nf < 4; nf++) {
        #pragma unroll
        for (int q = 0; q < 4; q++) sc[nf][q] *= scale;
        mx0 = fmaxf(mx0, fmaxf(sc[nf][0], sc[nf][1]));
        mx1 = fmaxf(mx1, fmaxf(sc[nf][2], sc[nf][3]));
    }
    mx0 = fmaxf(mx0, __shfl_xor_sync(0xffffffffu, mx0, 1));
    mx0 = fmaxf(mx0, __shfl_xor_sync(0xffffffffu, mx0, 2));
    mx1 = fmaxf(mx1, __shfl_xor_sync(0xffffffffu, mx1, 1));
    mx1 = fmaxf(mx1, __shfl_xor_sync(0xffffffffu, mx1, 2));
    if ((lid & 3) == 0) {
        pmax[R0 * 2 + wn2] = mx0;
        pmax[R1 * 2 + wn2] = mx1;
    }
    __syncthreads();
    const float gm0 = fmaxf(pmax[R0 * 2], pmax[R0 * 2 + 1]);
    const float gm1 = fmaxf(pmax[R1 * 2], pmax[R1 * 2 + 1]);

    float s0 = 0.f, s1 = 0.f;
    #pragma unroll
    for (int nf = 0; nf < 4; nf++) {
        sc[nf][0] = __expf(sc[nf][0] - gm0); s0 += sc[nf][0];
        sc[nf][1] = __expf(sc[nf][1] - gm0); s0 += sc[nf][1];
        sc[nf][2] = __expf(sc[nf][2] - gm1); s1 += sc[nf][2];
        sc[nf][3] = __expf(sc[nf][3] - gm1); s1 += sc[nf][3];
    }
    s0 += __shfl_xor_sync(0xffffffffu, s0, 1);
    s0 += __shfl_xor_sync(0xffffffffu, s0, 2);
    s1 += __shfl_xor_sync(0xffffffffu, s1, 1);
    s1 += __shfl_xor_sync(0xffffffffu, s1, 2);
    if ((lid & 3) == 0) {
        psum[R0 * 2 + wn2] = s0;
        psum[R1 * 2 + wn2] = s1;
    }
    __syncthreads();
    const float inv0 = 1.f / (psum[R0 * 2] + psum[R0 * 2 + 1]);
    const float inv1 = 1.f / (psum[R1 * 2] + psum[R1 * 2 + 1]);

    {
        char* Pp = smem + P_OFF;
        #pragma unroll
        for (int nf = 0; nf < 4; nf++) {
            const int col = wn2 * 32 + nf * 8 + (lid & 3) * 2;
            *(uint32_t*)(Pp + R0 * P_PITCH + col * 2) = packh2(sc[nf][0] * inv0, sc[nf][1] * inv0);
            *(uint32_t*)(Pp + R1 * P_PITCH + col * 2) = packh2(sc[nf][2] * inv1, sc[nf][3] * inv1);
        }
    }
    __syncthreads();

    uint32_t pa[4][4];
    #pragma unroll
    for (int j = 0; j < 4; j++)
        ldsm4(pa[j], sb + P_OFF + (wm * 16 + lr) * P_PITCH + j * 32 + lkb);

    const int prow0 = perm[head * TLEN + R0];
    const int prow8 = perm[head * TLEN + R1];
    const size_t obase0 = ((size_t)b * SEQ + prow0) * HDIM;
    const size_t obase8 = ((size_t)b * SEQ + prow8) * HDIM;

    for (int hcb = 0; hcb < 4; hcb++) {
        if (hcb < 3) {
            STAGE1(sb + ((hcb + 1) & 1) * AT_TILE, Vg, (hcb + 1) * 128);
            cp_commit();
            cp_wait1();
        } else {
            cp_wait0();
        }
        __syncthreads();

        const uint32_t vb = sb + (hcb & 1) * AT_TILE;
        float o[8][4];
        #pragma unroll
        for (int i = 0; i < 8; i++)
            #pragma unroll
            for (int q = 0; q < 4; q++) o[i][q] = 0.f;

        #pragma unroll
        for (int j = 0; j < 4; j++) {
            #pragma unroll
            for (int nf2 = 0; nf2 < 4; nf2++) {
                const uint32_t coff = (wn2 * 64 + nf2 * 16 + ((lid >> 4) & 1) * 8) * 2;
                uint32_t vh[4];
                ldsm4t(vh, vb + (j * 16 + lr) * AT_PITCH + coff);
                mma16816(o[2 * nf2],     pa[j], vh[0], vh[1]);
                mma16816(o[2 * nf2 + 1], pa[j], vh[2], vh[3]);
            }
        }

        const int hc = hcb * 128;
        #pragma unroll
        for (int nf = 0; nf < 8; nf++) {
            const int col = hc + wn2 * 64 + nf * 8 + (lid & 3) * 2;
            *(uint32_t*)(g_x16 + obase0 + col) = packh2(o[nf][0], o[nf][1]);
            *(uint32_t*)(g_x16 + obase8 + col) = packh2(o[nf][2], o[nf][3]);
        }
        __syncthreads();
    }
    #undef STAGE1
}

// ---------------------------------------------------------------------------
extern "C" void kernel_launch(void* const* d_in, const int* in_sizes, int n_in,
                              void* d_out, int out_size)
{
    const float* x  = (const float*)d_in[0];
    const float* Wq = (const float*)d_in[1];
    const float* bq = (const float*)d_in[2];
    const float* Wk = (const float*)d_in[3];
    const float* bk = (const float*)d_in[4];
    const float* Wv = (const float*)d_in[5];
    const float* bv = (const float*)d_in[6];
    const float* Wo = (const float*)d_in[7];
    const float* bo = (const float*)d_in[8];
    const int* perm = (const int*)d_in[9];
    float* out = (float*)d_out;

    __half *x16, *Wh, *qkv;
    cudaGetSymbolAddress((void**)&x16, g_x16);
    cudaGetSymbolAddress((void**)&Wh,  g_Wh);
    cudaGetSymbolAddress((void**)&qkv, g_QKV);

    cudaFuncSetAttribute(mma_gemm_kernel,
                         cudaFuncAttributeMaxDynamicSharedMemorySize, SMEM_REQ);
    cudaFuncSetAttribute(attn_kernel,
                         cudaFuncAttributeMaxDynamicSharedMemorySize, ATTN_SMEM);

    // all conversions in one launch (MLP=4 per thread)
    conv_all_kernel<<<XB4 + 4 * WB4, 256>>>(x, Wq, Wk, Wv, Wo, x16, Wh);

    // fused QKV projections (grid.z = 0..2) -> g_QKV fp16 (permuted rows)
    mma_gemm_kernel<<<dim3(HDIM / BN, NROWS / BM, 3), 256, SMEM_REQ>>>(
        x16, Wh, bq, bk, bv, nullptr, qkv, perm, 1);

    // tensorized attention -> g_x16 (fp16, un-permuted)
    attn_kernel<<<dim3(NHEAD, BATCH), 256, ATTN_SMEM>>>(perm);

    // output projection -> fp32 out
    mma_gemm_kernel<<<dim3(HDIM / BN, NROWS / BM, 1), 256, SMEM_REQ>>>(
        x16, Wh + 3 * (size_t)WN, bo, bo, bo, out, nullptr, perm, 0);
}